// round 6
// baseline (speedup 1.0000x reference)
#include <cuda_runtime.h>
#include <math.h>

// Problem constants (fixed by setup_inputs)
#define BB 8
#define CC 256
#define NN 16384
#define NN4 (NN/4)      // 4096
#define NB 16

#define TILE_N 64
#define NT4 16          // float4 per tile row (64 floats)
#define STRIDE4 17      // float4 stride per c-row (68 floats, conflict-free)
#define NTILES (NN/TILE_N)   // 256
#define JOBS (BB*NTILES)     // 2048

// Output layout: reprVecs [16,8,256], sims [16,8,1,128,128], selpos [8,1,128,128]
#define OUT_REPR   0
#define OUT_SIMS   (NB*BB*CC)                  // 32768
#define OUT_SELPOS (OUT_SIMS + NB*BB*NN)       // 2129920

// Scratch (no allocations allowed -> __device__ globals)
__device__ float g_score[BB*NN];
__device__ float g_repr2[2][BB][CC];   // double-buffered by iteration parity
__device__ float g_S2[2][BB];
__device__ float g_pv[BB*NTILES];      // per-tile argmax value of NEW score
__device__ int   g_pi[BB*NTILES];      // per-tile argmax index
__device__ unsigned g_job;             // dynamic job queue head
__device__ unsigned g_bar_count;
__device__ volatile unsigned g_bar_gen;

// ---------------------------------------------------------------------------
// Zero selpos output + barrier/queue state + accumulators (replay-safe).
__global__ void init_kernel(float* __restrict__ out) {
    int i = blockIdx.x * blockDim.x + threadIdx.x;
    if (i < BB*NN) out[OUT_SELPOS + i] = 0.0f;
    if (i < 2*BB*CC) ((float*)g_repr2)[i] = 0.0f;
    if (i < 2*BB) ((float*)g_S2)[i] = 0.0f;
    if (i == 0) { g_bar_count = 0; g_bar_gen = 0; g_job = 0; }
}

// ---------------------------------------------------------------------------
// Software grid barrier (all CTAs co-resident). Master also resets the job
// queue for the next iteration BEFORE the release store.
__device__ __forceinline__ void grid_barrier(unsigned nblocks, unsigned target) {
    __syncthreads();
    if (threadIdx.x == 0) {
        __threadfence();                       // release prior writes
        unsigned a = atomicAdd(&g_bar_count, 1u);
        if (a == nblocks - 1) {
            g_bar_count = 0;
            g_job = 0;                         // reset queue for next iter
            __threadfence();
            g_bar_gen = target;                // release
        } else {
            while (g_bar_gen < target) { }     // volatile poll (HW-sleepless ok)
            __threadfence();                   // acquire
        }
    }
    __syncthreads();
}

// ---------------------------------------------------------------------------
// Persistent kernel: all 16 iterations in one launch, dynamic job queue.
// Per iteration:
//   - warp w (w<8) reduces batch w's 256 per-tile argmax partials -> s_ind8[w]
//   - CTA bid<8 (batch=bid): emit+rezero repr(iter-1) (parity buffer), selpos+=1
//   - dynamic loop: fetch job j -> (b=j>>8, tile=j&255); reload rv_s on batch
//     change; run the 3-phase tile pipeline (stream+distance / sim+score+
//     argmax partial / weighted reduction); atomics into parity buffer
//   - ONE grid barrier
__global__ __launch_bounds__(256)
void persist_kernel(const float4* __restrict__ x4, const float* __restrict__ x,
                    float* __restrict__ out, unsigned nblocks) {
    const int t  = threadIdx.x;
    const int w  = t >> 5;          // warp 0..7
    const int l  = t & 31;
    const int n4 = l & 15;          // float4 index within row, 0..15
    const int c_off = l >> 4;       // 0..1

    extern __shared__ float sm[];
    float4* tile4 = (float4*)sm;                    // 256 * 17 float4
    float*  rv_s  = sm + CC*STRIDE4*4;              // 256
    float*  red   = rv_s + CC;                      // 512
    float*  sim_s = red + 512;                      // 64 (16B aligned)
    __shared__ float s_av[64];
    __shared__ int   s_ai[64];
    __shared__ int   s_ind8[8];
    __shared__ int   s_job;

    for (int iter = 0; iter < NB; iter++) {
        // ---- per-batch argmax: warp w handles batch w (deterministic) ----
        if (iter == 0) {
            if (t < 8) s_ind8[t] = NN / 2;
        } else {
            float bv = -3.0e38f; int bi = NN;
            const float* pv = g_pv + w*NTILES;
            const int*   pi = g_pi + w*NTILES;
            #pragma unroll
            for (int k = 0; k < 8; k++) {           // lane scans l*8 .. l*8+7
                int p = l*8 + k;
                float v = pv[p]; int idx = pi[p];
                if (v > bv || (v == bv && idx < bi)) { bv = v; bi = idx; }
            }
            #pragma unroll
            for (int off = 16; off > 0; off >>= 1) {
                float ov = __shfl_down_sync(0xffffffffu, bv, off);
                int   oi = __shfl_down_sync(0xffffffffu, bi, off);
                if (ov > bv || (ov == bv && oi < bi)) { bv = ov; bi = oi; }
            }
            if (l == 0) s_ind8[w] = bi;
        }
        __syncthreads();

        // ---- designated CTAs: batch b = blockIdx.x (<8) ----
        if (blockIdx.x < BB) {
            const int b = blockIdx.x;
            if (iter > 0) {
                const int p = (iter - 1) & 1;
                float S = g_S2[p][b];
                out[OUT_REPR + (size_t)(iter-1)*BB*CC + b*CC + t] =
                    g_repr2[p][b][t] / S;
                g_repr2[p][b][t] = 0.0f;       // buffer reused at iter+1
                if (t == 0) g_S2[p][b] = 0.0f;
            }
            if (t == 0) out[OUT_SELPOS + b*NN + s_ind8[b]] += 1.0f;
        }

        const int pb = iter & 1;
        int cur_b = -1;

        // ---- dynamic job loop ----
        while (true) {
            if (t == 0) s_job = (int)atomicAdd(&g_job, 1u);
            __syncthreads();
            const int j = s_job;
            if (j >= JOBS) break;                // uniform exit
            const int b    = j >> 8;             // tile-major within batch
            const int tile = j & 255;
            const int n0   = tile * TILE_N;

            if (b != cur_b) {                    // rv gather (L2-amortized)
                rv_s[t] = x[(size_t)b*CC*NN + (size_t)t*NN + s_ind8[b]];
                cur_b = b;
                __syncthreads();
            }

            // phase 1: warp w loads c = w*32 + step*2 + c_off, 16 float4/row
            const float4* xb = x4 + (size_t)b*CC*NN4 + (n0 >> 2) + n4;
            float4 acc = make_float4(0.f, 0.f, 0.f, 0.f);
            #pragma unroll
            for (int step = 0; step < 16; step++) {
                const int c = w*32 + step*2 + c_off;
                float4 v = xb[(size_t)c * NN4];
                tile4[c*STRIDE4 + n4] = v;
                float r = rv_s[c];
                float dx = v.x - r, dy = v.y - r, dz = v.z - r, dw = v.w - r;
                acc.x = fmaf(dx, dx, acc.x);
                acc.y = fmaf(dy, dy, acc.y);
                acc.z = fmaf(dz, dz, acc.z);
                acc.w = fmaf(dw, dw, acc.w);
            }
            acc.x += __shfl_down_sync(0xffffffffu, acc.x, 16);
            acc.y += __shfl_down_sync(0xffffffffu, acc.y, 16);
            acc.z += __shfl_down_sync(0xffffffffu, acc.z, 16);
            acc.w += __shfl_down_sync(0xffffffffu, acc.w, 16);
            if (c_off == 0) ((float4*)red)[w*16 + n4] = acc;
            __syncthreads();

            // phase 2: sim, sims output, score update, tile argmax partial
            if (t < TILE_N) {
                const int q = t >> 2, comp = t & 3;
                float d2 = 0.f;
                #pragma unroll
                for (int ww = 0; ww < 8; ww++) d2 += red[(ww*16 + q)*4 + comp];
                float sim = expf(-sqrtf(d2 + 1e-12f) * 0.05f);
                sim_s[t] = sim;
                out[OUT_SIMS + ((size_t)iter*BB + b)*NN + n0 + t] = sim;
                float* scp = g_score + (size_t)b*NN + n0 + t;
                float ns = 1.0f - sim;
                if (iter > 0) ns *= *scp;
                *scp = ns;
                s_av[t] = ns;
                s_ai[t] = n0 + t;
            }
            __syncthreads();

            // tile argmax of NEW score, 64 -> 1, first-index tie-break
            #pragma unroll
            for (int off = 32; off > 0; off >>= 1) {
                if (t < off) {
                    float ov = s_av[t+off]; int oi = s_ai[t+off];
                    if (ov > s_av[t] || (ov == s_av[t] && oi < s_ai[t])) {
                        s_av[t] = ov; s_ai[t] = oi;
                    }
                }
                __syncthreads();
            }
            if (t == 0) {
                g_pv[b*NTILES + tile] = s_av[0];
                g_pi[b*NTILES + tile] = s_ai[0];
            }

            // block-partial S -> atomic (warp 0)
            if (t < 32) {
                float s2 = sim_s[t] + sim_s[t + 32];
                #pragma unroll
                for (int off = 16; off > 0; off >>= 1)
                    s2 += __shfl_down_sync(0xffffffffu, s2, off);
                if (t == 0) atomicAdd(&g_S2[pb][b], s2);
            }

            // phase 3: repr_raw[c=t] += sum_n tile[c][n]*sim[n] (conflict-free
            // stride-17, 4 FMA chains hide latency)
            float r0 = 0.f, r1 = 0.f, r2 = 0.f, r3 = 0.f;
            const float4* trow = tile4 + t * STRIDE4;
            const float4* sv4  = (const float4*)sim_s;
            #pragma unroll
            for (int q = 0; q < NT4; q += 4) {
                float4 t0 = trow[q+0], s0 = sv4[q+0];
                float4 t1 = trow[q+1], s1 = sv4[q+1];
                float4 t2 = trow[q+2], s2 = sv4[q+2];
                float4 t3 = trow[q+3], s3 = sv4[q+3];
                r0 = fmaf(t0.x, s0.x, r0); r0 = fmaf(t0.y, s0.y, r0);
                r0 = fmaf(t0.z, s0.z, r0); r0 = fmaf(t0.w, s0.w, r0);
                r1 = fmaf(t1.x, s1.x, r1); r1 = fmaf(t1.y, s1.y, r1);
                r1 = fmaf(t1.z, s1.z, r1); r1 = fmaf(t1.w, s1.w, r1);
                r2 = fmaf(t2.x, s2.x, r2); r2 = fmaf(t2.y, s2.y, r2);
                r2 = fmaf(t2.z, s2.z, r2); r2 = fmaf(t2.w, s2.w, r2);
                r3 = fmaf(t3.x, s3.x, r3); r3 = fmaf(t3.y, s3.y, r3);
                r3 = fmaf(t3.z, s3.z, r3); r3 = fmaf(t3.w, s3.w, r3);
            }
            atomicAdd(&g_repr2[pb][b][t], (r0 + r1) + (r2 + r3));
            __syncthreads();   // protect tile4/sim_s/s_job before next job
        }

        grid_barrier(nblocks, (unsigned)(iter + 1));
    }

    // final repr emit for iter NB-1 (all atomics done: ordered by last barrier)
    if (blockIdx.x < BB) {
        const int b = blockIdx.x;
        const int p = (NB - 1) & 1;
        float S = g_S2[p][b];
        out[OUT_REPR + (size_t)(NB-1)*BB*CC + b*CC + t] = g_repr2[p][b][t] / S;
    }
}

// ---------------------------------------------------------------------------
extern "C" void kernel_launch(void* const* d_in, const int* in_sizes, int n_in,
                              void* d_out, int out_size) {
    const float* x = (const float*)d_in[0];
    // d_in[1] (prior) is provably unused: at i==0 the reference overwrites the
    // score with 1-sim and forces ind = N/2. d_in[2] (nbVec) is the constant 16.
    float* out = (float*)d_out;

    const size_t smem = (CC*STRIDE4*4 + CC + 512 + 64) * sizeof(float); // 72960 B
    cudaFuncSetAttribute(persist_kernel,
                         cudaFuncAttributeMaxDynamicSharedMemorySize, (int)smem);

    // Size the persistent grid so every CTA is co-resident (barrier safety).
    int dev = 0, sms = 148, occ = 1;
    cudaGetDevice(&dev);
    cudaDeviceGetAttribute(&sms, cudaDevAttrMultiProcessorCount, dev);
    cudaOccupancyMaxActiveBlocksPerMultiprocessor(&occ, persist_kernel, 256,
                                                  (int)smem);
    if (occ < 1) occ = 1;
    unsigned nblocks = (unsigned)(occ * sms);
    if (nblocks > JOBS) nblocks = JOBS;

    init_kernel<<<(BB*NN + 255) / 256, 256>>>(out);
    persist_kernel<<<nblocks, 256, smem>>>((const float4*)x, x, out, nblocks);
}

// round 10
// speedup vs baseline: 1.2060x; 1.2060x over previous
#include <cuda_runtime.h>
#include <math.h>

// Problem constants (fixed by setup_inputs)
#define BB 8
#define CC 256
#define NN 16384
#define NN4 (NN/4)      // 4096
#define NB 16

#define TILE_N 64
#define NT4 16          // float4 per tile row (64 floats)
#define STRIDE4 17      // float4 stride per c-row (68 floats, conflict-free)
#define NTILES (NN/TILE_N)   // 256
#define NCTAS (NTILES*BB)    // 2048 per iteration kernel

// Output layout: reprVecs [16,8,256], sims [16,8,1,128,128], selpos [8,1,128,128]
#define OUT_REPR   0
#define OUT_SIMS   (NB*BB*CC)                  // 32768
#define OUT_SELPOS (OUT_SIMS + NB*BB*NN)       // 2129920

// Scratch (no allocations allowed -> __device__ globals)
__device__ float g_score[BB*NN];
__device__ float g_repr[BB][CC];
__device__ float g_S[BB];
__device__ float g_rv[BB][CC];         // dense rv for the CURRENT iteration
__device__ float g_pv[BB*NTILES];      // per-tile argmax value of NEW score
__device__ int   g_pi[BB*NTILES];      // per-tile argmax index
__device__ int   g_ind[BB];            // selected index for the CURRENT iter
__device__ unsigned g_done;            // last-CTA detection counter

// ---------------------------------------------------------------------------
// Replay-safe init: zero selpos (and apply iter0's +1 at N/2), zero
// accumulators, gather iter0's rv (ind = N/2), reset done counter.
__global__ void init_kernel(const float* __restrict__ x, float* __restrict__ out) {
    int i = blockIdx.x * blockDim.x + threadIdx.x;
    if (i < BB*NN) {
        int n = i % NN;
        out[OUT_SELPOS + i] = (n == NN/2) ? 1.0f : 0.0f;
    }
    if (i < BB*CC) {
        ((float*)g_repr)[i] = 0.0f;
        int b = i / CC, c = i % CC;
        g_rv[b][c] = x[(size_t)b*CC*NN + (size_t)c*NN + NN/2];
    }
    if (i < BB) { g_S[i] = 0.0f; g_ind[i] = NN/2; }
    if (i == 0) g_done = 0;
}

// ---------------------------------------------------------------------------
// One iteration. grid = (NTILES, BB), 256 threads, one 64n x 256c tile each.
//   phase 0: load dense rv (coalesced 1KB; gathered by prev iter's last CTA)
//   phase 1: stream tile -> smem (LDG.128/STS.128) + per-n squared distance
//   phase 2: sim = exp(-sqrt(d2+eps)/20); emit sims; score update (atomic-free
//            -> selection chain bit-deterministic); argmax partial to s_av
//   warp 0 : tile argmax via shuffles -> g_pv/g_pi;  S partial -> atomicAdd
//   phase 3: repr_raw[c=t] += sum_n tile[c][n]*sim[n] (stride-17, 4 FMA chains)
//   tail   : threadfence + done-count; LAST CTA reduces argmax partials ->
//            g_ind + g_rv (next iter), bumps selpos, emits+resets repr/S/done.
__global__ __launch_bounds__(256)
void main_kernel(const float4* __restrict__ x4, const float* __restrict__ x,
                 float* __restrict__ out, int iter) {
    const int b    = blockIdx.y;
    const int tile = blockIdx.x;
    const int n0   = tile * TILE_N;
    const int t    = threadIdx.x;
    const int w    = t >> 5;        // warp 0..7
    const int l    = t & 31;
    const int n4   = l & 15;        // float4 index within row, 0..15
    const int c_off = l >> 4;       // 0..1

    extern __shared__ float sm[];
    float4* tile4 = (float4*)sm;                    // 256 * 17 float4
    float*  rv_s  = sm + CC*STRIDE4*4;              // 256
    float*  red   = rv_s + CC;                      // 512
    float*  sim_s = red + 512;                      // 64 (16B aligned)
    __shared__ float s_av[64];
    __shared__ int   s_ai[64];
    __shared__ int   s_ind8[8];
    __shared__ unsigned s_rank;

    // phase 0: dense rv load (coalesced)
    rv_s[t] = g_rv[b][t];
    __syncthreads();

    // phase 1: warp w loads c = w*32 + step*2 + c_off, 16 float4 per c-row
    const float4* xb = x4 + (size_t)b*CC*NN4 + (n0 >> 2) + n4;
    float4 acc = make_float4(0.f, 0.f, 0.f, 0.f);
    #pragma unroll
    for (int step = 0; step < 16; step++) {
        const int c = w*32 + step*2 + c_off;
        float4 v = xb[(size_t)c * NN4];
        tile4[c*STRIDE4 + n4] = v;
        float r = rv_s[c];
        float dx = v.x - r, dy = v.y - r, dz = v.z - r, dw = v.w - r;
        acc.x = fmaf(dx, dx, acc.x);
        acc.y = fmaf(dy, dy, acc.y);
        acc.z = fmaf(dz, dz, acc.z);
        acc.w = fmaf(dw, dw, acc.w);
    }
    acc.x += __shfl_down_sync(0xffffffffu, acc.x, 16);
    acc.y += __shfl_down_sync(0xffffffffu, acc.y, 16);
    acc.z += __shfl_down_sync(0xffffffffu, acc.z, 16);
    acc.w += __shfl_down_sync(0xffffffffu, acc.w, 16);
    if (c_off == 0) ((float4*)red)[w*16 + n4] = acc;
    __syncthreads();

    // phase 2: sim, sims output, score update, argmax partial
    if (t < TILE_N) {
        const int q = t >> 2, comp = t & 3;
        float d2 = 0.f;
        #pragma unroll
        for (int ww = 0; ww < 8; ww++) d2 += red[(ww*16 + q)*4 + comp];
        float sim = expf(-sqrtf(d2 + 1e-12f) * 0.05f);
        sim_s[t] = sim;
        out[OUT_SIMS + ((size_t)iter*BB + b)*NN + n0 + t] = sim;
        float* scp = g_score + (size_t)b*NN + n0 + t;
        float ns = 1.0f - sim;
        if (iter > 0) ns *= *scp;
        *scp = ns;
        s_av[t] = ns;
        s_ai[t] = n0 + t;
    }
    __syncthreads();

    // warp 0: tile argmax (first-index tie-break) + S partial, no extra syncs
    if (w == 0) {
        float v = s_av[l];  int vi = s_ai[l];
        float v2 = s_av[l+32]; int vi2 = s_ai[l+32];
        if (v2 > v) { v = v2; vi = vi2; }            // vi < vi2 always
        #pragma unroll
        for (int off = 16; off > 0; off >>= 1) {
            float ov = __shfl_down_sync(0xffffffffu, v,  off);
            int   oi = __shfl_down_sync(0xffffffffu, vi, off);
            if (ov > v || (ov == v && oi < vi)) { v = ov; vi = oi; }
        }
        float s2 = sim_s[l] + sim_s[l + 32];
        #pragma unroll
        for (int off = 16; off > 0; off >>= 1)
            s2 += __shfl_down_sync(0xffffffffu, s2, off);
        if (l == 0) {
            g_pv[b*NTILES + tile] = v;
            g_pi[b*NTILES + tile] = vi;
            atomicAdd(&g_S[b], s2);
        }
    }

    // phase 3: repr_raw[c=t] += sum_n tile[c][n]*sim[n] (conflict-free,
    // 4 accumulator chains hide FFMA latency)
    float r0 = 0.f, r1 = 0.f, r2 = 0.f, r3 = 0.f;
    const float4* trow = tile4 + t * STRIDE4;
    const float4* sv4  = (const float4*)sim_s;
    #pragma unroll
    for (int q = 0; q < NT4; q += 4) {
        float4 t0 = trow[q+0], s0 = sv4[q+0];
        float4 t1 = trow[q+1], s1 = sv4[q+1];
        float4 t2 = trow[q+2], s2 = sv4[q+2];
        float4 t3 = trow[q+3], s3 = sv4[q+3];
        r0 = fmaf(t0.x, s0.x, r0); r0 = fmaf(t0.y, s0.y, r0);
        r0 = fmaf(t0.z, s0.z, r0); r0 = fmaf(t0.w, s0.w, r0);
        r1 = fmaf(t1.x, s1.x, r1); r1 = fmaf(t1.y, s1.y, r1);
        r1 = fmaf(t1.z, s1.z, r1); r1 = fmaf(t1.w, s1.w, r1);
        r2 = fmaf(t2.x, s2.x, r2); r2 = fmaf(t2.y, s2.y, r2);
        r2 = fmaf(t2.z, s2.z, r2); r2 = fmaf(t2.w, s2.w, r2);
        r3 = fmaf(t3.x, s3.x, r3); r3 = fmaf(t3.y, s3.y, r3);
        r3 = fmaf(t3.z, s3.z, r3); r3 = fmaf(t3.w, s3.w, r3);
    }
    atomicAdd(&g_repr[b][t], (r0 + r1) + (r2 + r3));

    // ---- tail: last-CTA setup for next iteration ----
    __threadfence();                 // make this CTA's writes/atomics visible
    __syncthreads();
    if (t == 0) s_rank = atomicAdd(&g_done, 1u);
    __syncthreads();
    if (s_rank != NCTAS - 1) return;

    // LAST CTA: all other CTAs' fenced writes are visible.
    __threadfence();

    // 1) emit repr[iter] and reset accumulators (thread t = channel c)
    #pragma unroll
    for (int bb2 = 0; bb2 < BB; bb2++) {
        out[OUT_REPR + (size_t)iter*BB*CC + bb2*CC + t] =
            g_repr[bb2][t] / g_S[bb2];
        g_repr[bb2][t] = 0.0f;
    }
    __syncthreads();                 // g_S reads done before reset
    if (t < BB) g_S[t] = 0.0f;

    // 2) selection for next iteration: warp w reduces batch w's partials
    if (iter + 1 < NB) {
        float bv = -3.0e38f; int bi = NN;
        const float* pv = g_pv + w*NTILES;
        const int*   pi = g_pi + w*NTILES;
        #pragma unroll
        for (int k = 0; k < 8; k++) {
            int p = l*8 + k;
            float vv = pv[p]; int ii = pi[p];
            if (vv > bv || (vv == bv && ii < bi)) { bv = vv; bi = ii; }
        }
        #pragma unroll
        for (int off = 16; off > 0; off >>= 1) {
            float ov = __shfl_down_sync(0xffffffffu, bv, off);
            int   oi = __shfl_down_sync(0xffffffffu, bi, off);
            if (ov > bv || (ov == bv && oi < bi)) { bv = ov; bi = oi; }
        }
        if (l == 0) {
            g_ind[w] = bi;
            s_ind8[w] = bi;
            out[OUT_SELPOS + w*NN + bi] += 1.0f;
        }
        __syncthreads();

        // 3) gather next iteration's rv vectors densely (8 loads per thread)
        #pragma unroll
        for (int bb2 = 0; bb2 < BB; bb2++)
            g_rv[bb2][t] = x[(size_t)bb2*CC*NN + (size_t)t*NN + s_ind8[bb2]];
    }

    // 4) reset done counter for the next kernel
    if (t == 0) g_done = 0;
}

// ---------------------------------------------------------------------------
extern "C" void kernel_launch(void* const* d_in, const int* in_sizes, int n_in,
                              void* d_out, int out_size) {
    const float* x = (const float*)d_in[0];
    // d_in[1] (prior) is provably unused: at i==0 the reference overwrites the
    // score with 1-sim and forces ind = N/2. d_in[2] (nbVec) is the constant 16.
    float* out = (float*)d_out;

    const size_t smem = (CC*STRIDE4*4 + CC + 512 + 64) * sizeof(float); // 72960 B
    cudaFuncSetAttribute(main_kernel,
                         cudaFuncAttributeMaxDynamicSharedMemorySize, (int)smem);

    init_kernel<<<(BB*NN + 255) / 256, 256>>>(x, out);
    for (int i = 0; i < NB; i++)
        main_kernel<<<dim3(NTILES, BB), 256, smem>>>((const float4*)x, x, out, i);
}

// round 14
// speedup vs baseline: 1.4286x; 1.1846x over previous
#include <cuda_runtime.h>
#include <math.h>

// Problem constants (fixed by setup_inputs)
#define BB 8
#define CC 256
#define NN 16384
#define NN4 (NN/4)      // 4096
#define NB 16

#define TILE_N 64
#define NT4 16          // float4 per tile row (64 floats)
#define STRIDE4 17      // float4 stride per c-row (68 floats, conflict-free)
#define NTILES (NN/TILE_N)   // 256

// Output layout: reprVecs [16,8,256], sims [16,8,1,128,128], selpos [8,1,128,128]
#define OUT_REPR   0
#define OUT_SIMS   (NB*BB*CC)                  // 32768
#define OUT_SELPOS (OUT_SIMS + NB*BB*NN)       // 2129920

// Scratch (no allocations allowed -> __device__ globals)
__device__ float g_score[BB*NN];
__device__ float g_repr[BB][CC];
__device__ float g_S[BB];
__device__ float g_rv[BB][CC];         // dense rv for the CURRENT iteration
__device__ float g_pv[BB*NTILES];      // per-tile argmax value of NEW score
__device__ int   g_pi[BB*NTILES];      // per-tile argmax index

// ---------------------------------------------------------------------------
// Replay-safe init: zero selpos (+1 at N/2 = iter0 selection), zero
// accumulators, gather iter0's rv (ind = N/2).
__global__ void init_kernel(const float* __restrict__ x, float* __restrict__ out) {
    int i = blockIdx.x * blockDim.x + threadIdx.x;
    if (i < BB*NN) {
        int n = i % NN;
        out[OUT_SELPOS + i] = (n == NN/2) ? 1.0f : 0.0f;
    }
    if (i < BB*CC) {
        ((float*)g_repr)[i] = 0.0f;
        int b = i / CC, c = i % CC;
        g_rv[b][c] = x[(size_t)b*CC*NN + (size_t)c*NN + NN/2];
    }
    if (i < BB) g_S[i] = 0.0f;
}

// ---------------------------------------------------------------------------
// Cheap setup for iteration `iter` (launched for iter = 1..NB; one block per
// batch, 256 threads). Reads only the 256 per-tile argmax partials (not the
// full 16K score array -> that scan was the measured 7us latency bottleneck).
//   - emit repr[iter-1] = g_repr/g_S, reset accumulators
//   - iter < NB: reduce partials -> ind (first-index tie-break), bump selpos,
//     gather rv[b,:,ind] densely into g_rv for main's coalesced phase 0.
// Entirely atomic-free -> selection chain bit-deterministic.
__global__ void setup_kernel(const float* __restrict__ x,
                             float* __restrict__ out, int iter) {
    const int b = blockIdx.x;
    const int t = threadIdx.x;   // 256
    const int w = t >> 5;
    const int l = t & 31;
    __shared__ float s_v[8];
    __shared__ int   s_i[8];
    __shared__ int   s_ind;

    // 1) emit repr for iter-1, reset accumulators
    float S = g_S[b];
    out[OUT_REPR + (size_t)(iter-1)*BB*CC + b*CC + t] = g_repr[b][t] / S;
    g_repr[b][t] = 0.0f;
    if (t == 0) g_S[b] = 0.0f;
    if (iter >= NB) return;

    // 2) reduce 256 per-tile partials (thread t owns tile t)
    float v   = g_pv[b*NTILES + t];
    int   idx = g_pi[b*NTILES + t];
    #pragma unroll
    for (int off = 16; off > 0; off >>= 1) {
        float ov = __shfl_down_sync(0xffffffffu, v,   off);
        int   oi = __shfl_down_sync(0xffffffffu, idx, off);
        if (ov > v || (ov == v && oi < idx)) { v = ov; idx = oi; }
    }
    if (l == 0) { s_v[w] = v; s_i[w] = idx; }
    __syncthreads();
    if (t == 0) {
        float bv = s_v[0]; int bi = s_i[0];
        #pragma unroll
        for (int ww = 1; ww < 8; ww++)
            if (s_v[ww] > bv || (s_v[ww] == bv && s_i[ww] < bi)) {
                bv = s_v[ww]; bi = s_i[ww];
            }
        s_ind = bi;
        out[OUT_SELPOS + b*NN + bi] += 1.0f;
    }
    __syncthreads();

    // 3) dense rv gather for the next main pass
    g_rv[b][t] = x[(size_t)b*CC*NN + (size_t)t*NN + s_ind];
}

// ---------------------------------------------------------------------------
// One iteration, NO cross-CTA synchronization (measured 4.2 TB/s in R4; the
// fused-tail/persistent variants with in-kernel sync measured 2.5 TB/s).
// grid = (NTILES, BB), 256 threads, one 64n x 256c tile each.
//   phase 0: dense rv load (coalesced 1KB)
//   phase 1: stream tile -> smem (LDG.128/STS.128) + per-n squared distance
//   phase 2: sim = exp(-sqrt(d2+eps)/20); emit sims; score update; partial
//   warp 0 : tile argmax via shuffles -> g_pv/g_pi;  S partial -> atomicAdd
//   phase 3: repr_raw[c=t] += sum_n tile[c][n]*sim[n] (stride-17, 4 FMA chains)
__global__ __launch_bounds__(256)
void main_kernel(const float4* __restrict__ x4, float* __restrict__ out,
                 int iter) {
    const int b    = blockIdx.y;
    const int tile = blockIdx.x;
    const int n0   = tile * TILE_N;
    const int t    = threadIdx.x;
    const int w    = t >> 5;        // warp 0..7
    const int l    = t & 31;
    const int n4   = l & 15;        // float4 index within row, 0..15
    const int c_off = l >> 4;       // 0..1

    extern __shared__ float sm[];
    float4* tile4 = (float4*)sm;                    // 256 * 17 float4
    float*  rv_s  = sm + CC*STRIDE4*4;              // 256
    float*  red   = rv_s + CC;                      // 512
    float*  sim_s = red + 512;                      // 64 (16B aligned)
    __shared__ float s_av[64];
    __shared__ int   s_ai[64];

    // phase 0: dense rv load (coalesced)
    rv_s[t] = g_rv[b][t];
    __syncthreads();

    // phase 1: warp w loads c = w*32 + step*2 + c_off, 16 float4 per c-row
    const float4* xb = x4 + (size_t)b*CC*NN4 + (n0 >> 2) + n4;
    float4 acc = make_float4(0.f, 0.f, 0.f, 0.f);
    #pragma unroll
    for (int step = 0; step < 16; step++) {
        const int c = w*32 + step*2 + c_off;
        float4 v = xb[(size_t)c * NN4];
        tile4[c*STRIDE4 + n4] = v;
        float r = rv_s[c];
        float dx = v.x - r, dy = v.y - r, dz = v.z - r, dw = v.w - r;
        acc.x = fmaf(dx, dx, acc.x);
        acc.y = fmaf(dy, dy, acc.y);
        acc.z = fmaf(dz, dz, acc.z);
        acc.w = fmaf(dw, dw, acc.w);
    }
    acc.x += __shfl_down_sync(0xffffffffu, acc.x, 16);
    acc.y += __shfl_down_sync(0xffffffffu, acc.y, 16);
    acc.z += __shfl_down_sync(0xffffffffu, acc.z, 16);
    acc.w += __shfl_down_sync(0xffffffffu, acc.w, 16);
    if (c_off == 0) ((float4*)red)[w*16 + n4] = acc;
    __syncthreads();

    // phase 2: sim, sims output, score update, argmax partial (atomic-free)
    if (t < TILE_N) {
        const int q = t >> 2, comp = t & 3;
        float d2 = 0.f;
        #pragma unroll
        for (int ww = 0; ww < 8; ww++) d2 += red[(ww*16 + q)*4 + comp];
        float sim = expf(-sqrtf(d2 + 1e-12f) * 0.05f);
        sim_s[t] = sim;
        out[OUT_SIMS + ((size_t)iter*BB + b)*NN + n0 + t] = sim;
        float* scp = g_score + (size_t)b*NN + n0 + t;
        float ns = 1.0f - sim;
        if (iter > 0) ns *= *scp;
        *scp = ns;
        s_av[t] = ns;
        s_ai[t] = n0 + t;
    }
    __syncthreads();

    // warp 0: tile argmax (first-index tie-break) + S partial, no extra syncs
    if (w == 0) {
        float v = s_av[l];  int vi = s_ai[l];
        float v2 = s_av[l+32]; int vi2 = s_ai[l+32];
        if (v2 > v) { v = v2; vi = vi2; }            // vi < vi2 always
        #pragma unroll
        for (int off = 16; off > 0; off >>= 1) {
            float ov = __shfl_down_sync(0xffffffffu, v,  off);
            int   oi = __shfl_down_sync(0xffffffffu, vi, off);
            if (ov > v || (ov == v && oi < vi)) { v = ov; vi = oi; }
        }
        float s2 = sim_s[l] + sim_s[l + 32];
        #pragma unroll
        for (int off = 16; off > 0; off >>= 1)
            s2 += __shfl_down_sync(0xffffffffu, s2, off);
        if (l == 0) {
            g_pv[b*NTILES + tile] = v;
            g_pi[b*NTILES + tile] = vi;
            atomicAdd(&g_S[b], s2);
        }
    }

    // phase 3: repr_raw[c=t] += sum_n tile[c][n]*sim[n] (conflict-free,
    // 4 accumulator chains hide FFMA latency)
    float r0 = 0.f, r1 = 0.f, r2 = 0.f, r3 = 0.f;
    const float4* trow = tile4 + t * STRIDE4;
    const float4* sv4  = (const float4*)sim_s;
    #pragma unroll
    for (int q = 0; q < NT4; q += 4) {
        float4 t0 = trow[q+0], s0 = sv4[q+0];
        float4 t1 = trow[q+1], s1 = sv4[q+1];
        float4 t2 = trow[q+2], s2 = sv4[q+2];
        float4 t3 = trow[q+3], s3 = sv4[q+3];
        r0 = fmaf(t0.x, s0.x, r0); r0 = fmaf(t0.y, s0.y, r0);
        r0 = fmaf(t0.z, s0.z, r0); r0 = fmaf(t0.w, s0.w, r0);
        r1 = fmaf(t1.x, s1.x, r1); r1 = fmaf(t1.y, s1.y, r1);
        r1 = fmaf(t1.z, s1.z, r1); r1 = fmaf(t1.w, s1.w, r1);
        r2 = fmaf(t2.x, s2.x, r2); r2 = fmaf(t2.y, s2.y, r2);
        r2 = fmaf(t2.z, s2.z, r2); r2 = fmaf(t2.w, s2.w, r2);
        r3 = fmaf(t3.x, s3.x, r3); r3 = fmaf(t3.y, s3.y, r3);
        r3 = fmaf(t3.z, s3.z, r3); r3 = fmaf(t3.w, s3.w, r3);
    }
    atomicAdd(&g_repr[b][t], (r0 + r1) + (r2 + r3));
}

// ---------------------------------------------------------------------------
extern "C" void kernel_launch(void* const* d_in, const int* in_sizes, int n_in,
                              void* d_out, int out_size) {
    const float* x = (const float*)d_in[0];
    // d_in[1] (prior) is provably unused: at i==0 the reference overwrites the
    // score with 1-sim and forces ind = N/2. d_in[2] (nbVec) is the constant 16.
    float* out = (float*)d_out;

    const size_t smem = (CC*STRIDE4*4 + CC + 512 + 64) * sizeof(float); // 72960 B
    cudaFuncSetAttribute(main_kernel,
                         cudaFuncAttributeMaxDynamicSharedMemorySize, (int)smem);

    init_kernel<<<(BB*NN + 255) / 256, 256>>>(x, out);
    main_kernel<<<dim3(NTILES, BB), 256, smem>>>((const float4*)x, out, 0);
    for (int i = 1; i < NB; i++) {
        setup_kernel<<<BB, 256>>>(x, out, i);
        main_kernel<<<dim3(NTILES, BB), 256, smem>>>((const float4*)x, out, i);
    }
    setup_kernel<<<BB, 256>>>(x, out, NB);   // final repr normalize only
}

// round 16
// speedup vs baseline: 1.5215x; 1.0651x over previous
#include <cuda_runtime.h>
#include <math.h>

// Problem constants (fixed by setup_inputs)
#define BB 8
#define CC 256
#define NN 16384
#define NN4 (NN/4)      // 4096
#define NB 16

#define TILE_N 32
#define NT4 8           // float4 per tile row (32 floats)
#define NTILES (NN/TILE_N)   // 512

// XOR-swizzled tile index (no padding): row c, float4-column q (0..7).
// Store phase (fixed c, q=0..7) -> 8 distinct banks; read phase (thread t=c,
// q fixed) -> q^(t&7) permutation over 8 consecutive t -> conflict-free.
#define TIDX(c, q) ((c)*NT4 + ((q) ^ ((c) & 7)))

// Output layout: reprVecs [16,8,256], sims [16,8,1,128,128], selpos [8,1,128,128]
#define OUT_REPR   0
#define OUT_SIMS   (NB*BB*CC)                  // 32768
#define OUT_SELPOS (OUT_SIMS + NB*BB*NN)       // 2129920

// Scratch (no allocations allowed -> __device__ globals)
__device__ float g_score[BB*NN];
__device__ float g_repr[BB][CC];
__device__ float g_S[BB];
__device__ float g_rv[BB][CC];         // dense rv for the CURRENT iteration
__device__ float g_pv[BB*NTILES];      // per-tile argmax value of NEW score
__device__ int   g_pi[BB*NTILES];      // per-tile argmax index

// ---------------------------------------------------------------------------
// Replay-safe init: zero selpos (+1 at N/2 = iter0 selection), zero
// accumulators, gather iter0's rv (ind = N/2).
__global__ void init_kernel(const float* __restrict__ x, float* __restrict__ out) {
    int i = blockIdx.x * blockDim.x + threadIdx.x;
    if (i < BB*NN) {
        int n = i % NN;
        out[OUT_SELPOS + i] = (n == NN/2) ? 1.0f : 0.0f;
    }
    if (i < BB*CC) {
        ((float*)g_repr)[i] = 0.0f;
        int b = i / CC, c = i % CC;
        g_rv[b][c] = x[(size_t)b*CC*NN + (size_t)c*NN + NN/2];
    }
    if (i < BB) g_S[i] = 0.0f;
}

// ---------------------------------------------------------------------------
// Cheap setup for iteration `iter` (one block per batch, 256 threads).
// Reads only the 512 per-tile argmax partials (2 per thread).
//   - emit repr[iter-1] = g_repr/g_S, reset accumulators
//   - iter < NB: reduce partials -> ind (first-index tie-break), bump selpos,
//     gather rv[b,:,ind] densely into g_rv for main's coalesced phase 0.
// Entirely atomic-free -> selection chain bit-deterministic.
__global__ void setup_kernel(const float* __restrict__ x,
                             float* __restrict__ out, int iter) {
    const int b = blockIdx.x;
    const int t = threadIdx.x;   // 256
    const int w = t >> 5;
    const int l = t & 31;
    __shared__ float s_v[8];
    __shared__ int   s_i[8];
    __shared__ int   s_ind;

    // 1) emit repr for iter-1, reset accumulators
    float S = g_S[b];
    out[OUT_REPR + (size_t)(iter-1)*BB*CC + b*CC + t] = g_repr[b][t] / S;
    g_repr[b][t] = 0.0f;
    if (t == 0) g_S[b] = 0.0f;
    if (iter >= NB) return;

    // 2) reduce 512 per-tile partials (thread t pre-folds tiles t and t+256;
    //    tile t's indices < tile t+256's, so standard compare keeps first-max)
    float v   = g_pv[b*NTILES + t];
    int   idx = g_pi[b*NTILES + t];
    {
        float v2 = g_pv[b*NTILES + 256 + t];
        int   i2 = g_pi[b*NTILES + 256 + t];
        if (v2 > v || (v2 == v && i2 < idx)) { v = v2; idx = i2; }
    }
    #pragma unroll
    for (int off = 16; off > 0; off >>= 1) {
        float ov = __shfl_down_sync(0xffffffffu, v,   off);
        int   oi = __shfl_down_sync(0xffffffffu, idx, off);
        if (ov > v || (ov == v && oi < idx)) { v = ov; idx = oi; }
    }
    if (l == 0) { s_v[w] = v; s_i[w] = idx; }
    __syncthreads();
    if (t == 0) {
        float bv = s_v[0]; int bi = s_i[0];
        #pragma unroll
        for (int ww = 1; ww < 8; ww++)
            if (s_v[ww] > bv || (s_v[ww] == bv && s_i[ww] < bi)) {
                bv = s_v[ww]; bi = s_i[ww];
            }
        s_ind = bi;
        out[OUT_SELPOS + b*NN + bi] += 1.0f;
    }
    __syncthreads();

    // 3) dense rv gather for the next main pass
    g_rv[b][t] = x[(size_t)b*CC*NN + (size_t)t*NN + s_ind];
}

// ---------------------------------------------------------------------------
// One iteration, NO cross-CTA synchronization (in-kernel sync measured 1.7x
// slower in R6/R10). grid = (NTILES, BB) = 4096 CTAs, 256 threads, one
// 32n x 256c tile each. Smem 34.9KB (XOR swizzle, no padding) -> 6 CTAs/SM
// (was 3 at 73KB -> occupancy was the measured 41%-DRAM bottleneck in R14).
//   phase 0: dense rv load (coalesced 1KB)
//   phase 1: 8x LDG.128 -> swizzled smem + per-n squared distance (warp fold)
//   phase 2: sim = exp(-sqrt(d2+eps)/20); sims out; score update; partial
//   warp 0 : tile argmax + S partial via shuffles (no extra syncs)
//   phase 3: repr_raw[c=t] += sum_n tile[c][n]*sim[n] (swizzled, 4 FMA chains)
__global__ __launch_bounds__(256)
void main_kernel(const float4* __restrict__ x4, float* __restrict__ out,
                 int iter) {
    const int b    = blockIdx.y;
    const int tile = blockIdx.x;
    const int n0   = tile * TILE_N;
    const int t    = threadIdx.x;
    const int w    = t >> 5;        // warp 0..7
    const int l    = t & 31;
    const int n4   = l & 7;         // float4 index within row, 0..7
    const int c_off = l >> 3;       // 0..3

    extern __shared__ float sm[];
    float4* tile4 = (float4*)sm;                    // 256*8 float4 = 32KB
    float*  rv_s  = sm + CC*NT4*4;                  // 256
    float*  red   = rv_s + CC;                      // 8 warps * 8 n4 * 4 = 256
    float*  sim_s = red + 256;                      // 32 (16B aligned)
    __shared__ float s_av[TILE_N];
    __shared__ int   s_ai[TILE_N];

    // phase 0: dense rv load (coalesced; g_rv is 8KB L2-resident)
    rv_s[t] = g_rv[b][t];
    __syncthreads();

    // phase 1: warp w loads c = w*32 + step*4 + c_off, 8 float4 per c-row
    const float4* xb = x4 + (size_t)b*CC*NN4 + (n0 >> 2) + n4;
    float4 acc = make_float4(0.f, 0.f, 0.f, 0.f);
    #pragma unroll
    for (int step = 0; step < 8; step++) {
        const int c = w*32 + step*4 + c_off;
        float4 v = xb[(size_t)c * NN4];
        tile4[TIDX(c, n4)] = v;
        float r = rv_s[c];
        float dx = v.x - r, dy = v.y - r, dz = v.z - r, dw = v.w - r;
        acc.x = fmaf(dx, dx, acc.x);
        acc.y = fmaf(dy, dy, acc.y);
        acc.z = fmaf(dz, dz, acc.z);
        acc.w = fmaf(dw, dw, acc.w);
    }
    // fold the 4 c_off groups (lanes l, l+8, l+16, l+24 share n4)
    acc.x += __shfl_down_sync(0xffffffffu, acc.x, 16);
    acc.y += __shfl_down_sync(0xffffffffu, acc.y, 16);
    acc.z += __shfl_down_sync(0xffffffffu, acc.z, 16);
    acc.w += __shfl_down_sync(0xffffffffu, acc.w, 16);
    acc.x += __shfl_down_sync(0xffffffffu, acc.x, 8);
    acc.y += __shfl_down_sync(0xffffffffu, acc.y, 8);
    acc.z += __shfl_down_sync(0xffffffffu, acc.z, 8);
    acc.w += __shfl_down_sync(0xffffffffu, acc.w, 8);
    if (l < 8) ((float4*)red)[w*8 + l] = acc;
    __syncthreads();

    // phase 2: sim, sims output, score update, argmax partial (atomic-free)
    if (t < TILE_N) {
        const int q = t >> 2, comp = t & 3;
        float d2 = 0.f;
        #pragma unroll
        for (int ww = 0; ww < 8; ww++) d2 += red[(ww*8 + q)*4 + comp];
        float sim = expf(-sqrtf(d2 + 1e-12f) * 0.05f);
        sim_s[t] = sim;
        out[OUT_SIMS + ((size_t)iter*BB + b)*NN + n0 + t] = sim;
        float* scp = g_score + (size_t)b*NN + n0 + t;
        float ns = 1.0f - sim;
        if (iter > 0) ns *= *scp;
        *scp = ns;
        s_av[t] = ns;
        s_ai[t] = n0 + t;
    }
    __syncthreads();

    // warp 0: tile argmax (first-index tie-break) + S partial, no extra syncs
    if (w == 0) {
        float v = s_av[l];  int vi = s_ai[l];
        #pragma unroll
        for (int off = 16; off > 0; off >>= 1) {
            float ov = __shfl_down_sync(0xffffffffu, v,  off);
            int   oi = __shfl_down_sync(0xffffffffu, vi, off);
            if (ov > v || (ov == v && oi < vi)) { v = ov; vi = oi; }
        }
        float s2 = sim_s[l];
        #pragma unroll
        for (int off = 16; off > 0; off >>= 1)
            s2 += __shfl_down_sync(0xffffffffu, s2, off);
        if (l == 0) {
            g_pv[b*NTILES + tile] = v;
            g_pi[b*NTILES + tile] = vi;
            atomicAdd(&g_S[b], s2);
        }
    }

    // phase 3: repr_raw[c=t] += sum_n tile[c][n]*sim[n] (swizzled reads,
    // 4 accumulator chains hide FFMA latency)
    float r0 = 0.f, r1 = 0.f, r2 = 0.f, r3 = 0.f;
    const float4* sv4 = (const float4*)sim_s;
    const int tb = t * NT4, tx = t & 7;
    {
        float4 t0 = tile4[tb + (0 ^ tx)], s0 = sv4[0];
        float4 t1 = tile4[tb + (1 ^ tx)], s1 = sv4[1];
        float4 t2 = tile4[tb + (2 ^ tx)], s2 = sv4[2];
        float4 t3 = tile4[tb + (3 ^ tx)], s3 = sv4[3];
        float4 t4 = tile4[tb + (4 ^ tx)], s4 = sv4[4];
        float4 t5 = tile4[tb + (5 ^ tx)], s5 = sv4[5];
        float4 t6 = tile4[tb + (6 ^ tx)], s6 = sv4[6];
        float4 t7 = tile4[tb + (7 ^ tx)], s7 = sv4[7];
        r0 = fmaf(t0.x, s0.x, r0); r0 = fmaf(t0.y, s0.y, r0);
        r0 = fmaf(t0.z, s0.z, r0); r0 = fmaf(t0.w, s0.w, r0);
        r1 = fmaf(t1.x, s1.x, r1); r1 = fmaf(t1.y, s1.y, r1);
        r1 = fmaf(t1.z, s1.z, r1); r1 = fmaf(t1.w, s1.w, r1);
        r2 = fmaf(t2.x, s2.x, r2); r2 = fmaf(t2.y, s2.y, r2);
        r2 = fmaf(t2.z, s2.z, r2); r2 = fmaf(t2.w, s2.w, r2);
        r3 = fmaf(t3.x, s3.x, r3); r3 = fmaf(t3.y, s3.y, r3);
        r3 = fmaf(t3.z, s3.z, r3); r3 = fmaf(t3.w, s3.w, r3);
        r0 = fmaf(t4.x, s4.x, r0); r0 = fmaf(t4.y, s4.y, r0);
        r0 = fmaf(t4.z, s4.z, r0); r0 = fmaf(t4.w, s4.w, r0);
        r1 = fmaf(t5.x, s5.x, r1); r1 = fmaf(t5.y, s5.y, r1);
        r1 = fmaf(t5.z, s5.z, r1); r1 = fmaf(t5.w, s5.w, r1);
        r2 = fmaf(t6.x, s6.x, r2); r2 = fmaf(t6.y, s6.y, r2);
        r2 = fmaf(t6.z, s6.z, r2); r2 = fmaf(t6.w, s6.w, r2);
        r3 = fmaf(t7.x, s7.x, r3); r3 = fmaf(t7.y, s7.y, r3);
        r3 = fmaf(t7.z, s7.z, r3); r3 = fmaf(t7.w, s7.w, r3);
    }
    atomicAdd(&g_repr[b][t], (r0 + r1) + (r2 + r3));
}

// ---------------------------------------------------------------------------
extern "C" void kernel_launch(void* const* d_in, const int* in_sizes, int n_in,
                              void* d_out, int out_size) {
    const float* x = (const float*)d_in[0];
    // d_in[1] (prior) is provably unused: at i==0 the reference overwrites the
    // score with 1-sim and forces ind = N/2. d_in[2] (nbVec) is the constant 16.
    float* out = (float*)d_out;

    const size_t smem = (CC*NT4*4 + CC + 256 + 32) * sizeof(float); // 34944 B
    cudaFuncSetAttribute(main_kernel,
                         cudaFuncAttributeMaxDynamicSharedMemorySize, (int)smem);

    init_kernel<<<(BB*NN + 255) / 256, 256>>>(x, out);
    main_kernel<<<dim3(NTILES, BB), 256, smem>>>((const float4*)x, out, 0);
    for (int i = 1; i < NB; i++) {
        setup_kernel<<<BB, 256>>>(x, out, i);
        main_kernel<<<dim3(NTILES, BB), 256, smem>>>((const float4*)x, out, i);
    }
    setup_kernel<<<BB, 256>>>(x, out, NB);   // final repr normalize only
}